// round 16
// baseline (speedup 1.0000x reference)
#include <cuda_runtime.h>

#define BB 1024
#define SS 192
#define DD 512
#define NLAYERS 3
#define LN_EPS 1e-5f

// Allocation-free scratch (device globals, permitted by harness rules).
__device__ int   g_start[BB];
__device__ int   g_end[BB];
__device__ float g_add[SS * DD];   // combined add table: [pos][d]

// ---------------------------------------------------------------------------
// Kernel 1 (fused prologue), v2:
//   blocks [0, ADD4_BLOCKS)           : build g_add table, float4-vectorized
//   blocks [ADD4_BLOCKS, +BND_BLOCKS) : per-batch start/end from mask,
//                                       loads hoisted ahead of ballots
// ---------------------------------------------------------------------------
#define ADD4_BLOCKS ((SS * DD / 4 + 255) / 256)   // 96
#define BND_BLOCKS  ((BB + 7) / 8)                // 128 (8 warps/block)

__global__ void prologue_kernel(const int*   __restrict__ mask,
                                const float* __restrict__ item,
                                const float* __restrict__ layer,
                                const float* __restrict__ temporal) {
    if (blockIdx.x < ADD4_BLOCKS) {
        int idx4 = blockIdx.x * blockDim.x + threadIdx.x;   // float4 index
        if (idx4 >= SS * DD / 4) return;
        int base = idx4 * 4;
        int pos  = base / DD;        // all 4 lanes share pos (DD % 4 == 0)
        int d    = base % DD;
        int it   = pos / NLAYERS;
        int ly   = pos % NLAYERS;
        float4 iv = *(const float4*)(item     + it * DD + d);
        float4 lv = *(const float4*)(layer    + ly * DD + d);
        float4 tv = *(const float4*)(temporal + it * DD + d);
        float4 r;
        r.x = iv.x + lv.x + tv.x;
        r.y = iv.y + lv.y + tv.y;
        r.z = iv.z + lv.z + tv.z;
        r.w = iv.w + lv.w + tv.w;
        *(float4*)(g_add + base) = r;
        return;
    }

    // bounds part: one warp per batch row; all chunk loads issued up front
    int blk  = blockIdx.x - ADD4_BLOCKS;
    int b    = blk * (blockDim.x >> 5) + (threadIdx.x >> 5);
    int lane = threadIdx.x & 31;
    if (b >= BB) return;
    const int* m = mask + b * SS;

    int v[SS / 32];
#pragma unroll
    for (int c = 0; c < SS / 32; ++c) v[c] = m[c * 32 + lane];   // independent LDGs

    int start = SS;
    int end   = 0;
#pragma unroll
    for (int c = 0; c < SS / 32; ++c) {
        unsigned bal = __ballot_sync(0xffffffffu, v[c] != 0);
        if (bal) {
            int first = c * 32 + __ffs(bal) - 1;
            int last  = c * 32 + 31 - __clz(bal);
            if (start == SS) start = first;
            end = last + 1;
        }
    }
    if (lane == 0) {
        g_start[b] = start;
        g_end[b]   = end;
    }
}

// ---------------------------------------------------------------------------
// Kernel 2: fused add + LayerNorm + mask. One warp per (b,s) row.
// Mask-free predicate from L1-hot bounds tables (contiguous left-padding).
// w/bias staged in shared memory once per block (best measured config, R14).
// ---------------------------------------------------------------------------
__global__ __launch_bounds__(256, 6) void fused_kernel(
    const float* __restrict__ tok,
    const float* __restrict__ w,
    const float* __restrict__ bias,
    float*       __restrict__ out)
{
    __shared__ float s_w[DD];
    __shared__ float s_b[DD];

    int tid = threadIdx.x;
    // 256 threads load 512+512 floats: 2 per thread per array.
    s_w[tid]       = __ldg(w + tid);
    s_w[tid + 256] = __ldg(w + tid + 256);
    s_b[tid]       = __ldg(bias + tid);
    s_b[tid + 256] = __ldg(bias + tid + 256);
    __syncthreads();

    int gwarp = (blockIdx.x * blockDim.x + tid) >> 5;
    int lane  = tid & 31;
    if (gwarp >= BB * SS) return;

    int b = gwarp / SS;
    int s = gwarp % SS;
    size_t base = (size_t)gwarp * DD;
    float4* o = (float4*)(out + base);

    int st = g_start[b];
    int en = g_end[b];
    bool active = (s >= st) && (s < en);   // == (mask != 0) == in_range

    if (!active) {
        // output = normed * 0 -> just write zeros, skip the token read.
        float4 z = make_float4(0.f, 0.f, 0.f, 0.f);
#pragma unroll
        for (int k = 0; k < 4; ++k) __stcs(&o[lane + k * 32], z);
        return;
    }

    int pos = s - st;

    const float4* t = (const float4*)(tok + base);
    const float4* a = (const float4*)(g_add + pos * DD);

    float4 e[4];
#pragma unroll
    for (int k = 0; k < 4; ++k) e[k] = __ldcs(&t[lane + k * 32]);

#pragma unroll
    for (int k = 0; k < 4; ++k) {
        float4 av = __ldg(&a[lane + k * 32]);
        e[k].x += av.x; e[k].y += av.y; e[k].z += av.z; e[k].w += av.w;
    }

    float sum = 0.f, sq = 0.f;
#pragma unroll
    for (int k = 0; k < 4; ++k) {
        sum += e[k].x + e[k].y + e[k].z + e[k].w;
        sq  += e[k].x * e[k].x + e[k].y * e[k].y
             + e[k].z * e[k].z + e[k].w * e[k].w;
    }
#pragma unroll
    for (int off = 16; off >= 1; off >>= 1) {
        sum += __shfl_xor_sync(0xffffffffu, sum, off);
        sq  += __shfl_xor_sync(0xffffffffu, sq,  off);
    }

    const float inv_d = 1.0f / (float)DD;
    float mu   = sum * inv_d;
    float var  = sq * inv_d - mu * mu;
    float rstd = rsqrtf(var + LN_EPS);

    const float4* swv = (const float4*)s_w;
    const float4* sbv = (const float4*)s_b;
#pragma unroll
    for (int k = 0; k < 4; ++k) {
        float4 W  = swv[lane + k * 32];
        float4 Bv = sbv[lane + k * 32];
        float4 r;
        r.x = (e[k].x - mu) * rstd * W.x + Bv.x;
        r.y = (e[k].y - mu) * rstd * W.y + Bv.y;
        r.z = (e[k].z - mu) * rstd * W.z + Bv.z;
        r.w = (e[k].w - mu) * rstd * W.w + Bv.w;
        __stcs(&o[lane + k * 32], r);
    }
}

// ---------------------------------------------------------------------------
// Launch
// ---------------------------------------------------------------------------
extern "C" void kernel_launch(void* const* d_in, const int* in_sizes, int n_in,
                              void* d_out, int out_size) {
    const float* tok      = (const float*)d_in[0];
    const int*   mask     = (const int*)  d_in[1];
    const float* item     = (const float*)d_in[2];
    const float* layer    = (const float*)d_in[3];
    const float* temporal = (const float*)d_in[4];
    const float* w        = (const float*)d_in[5];
    const float* bias     = (const float*)d_in[6];
    float*       out      = (float*)d_out;

    prologue_kernel<<<ADD4_BLOCKS + BND_BLOCKS, 256>>>(mask, item, layer, temporal);

    int rows = BB * SS;                // one warp per row
    int warps_per_block = 256 / 32;    // 8
    int blocks = (rows + warps_per_block - 1) / warps_per_block;
    fused_kernel<<<blocks, 256>>>(tok, w, bias, out);
}